// round 13
// baseline (speedup 1.0000x reference)
#include <cuda_runtime.h>
#include <cuda_bf16.h>
#include <cstdint>

// Problem constants (fixed by reference)
#define BS   24
#define CREP 16
#define HH   320
#define WW   320
#define HWSZ (HH * WW)               // 102400
#define NPIX (BS * HWSZ)             // 2457600
#define NMP  4
#define NSEG 16                      // NUM_CLASSES * NUM_MICRO_PROTO
#define NWARP 8                      // warps per block
#define CPAD 18                      // padded channel stride (bank-conflict-free f32x2)

// Scratch (no allocations allowed): global segment sums + counts
__device__ float g_sums[NSEG * CREP];
__device__ float g_counts[NSEG];

__global__ void zero_kernel() {
    int t = threadIdx.x;
    if (t < NSEG * CREP) g_sums[t] = 0.0f;
    if (t < NSEG)        g_counts[t] = 0.0f;
}

__device__ __forceinline__ uint32_t smem_u32(const void* p) {
    uint32_t a;
    asm("{ .reg .u64 t; cvta.to.shared.u64 t, %1; cvt.u32.u64 %0, t; }"
        : "=r"(a) : "l"(p));
    return a;
}

__global__ __launch_bounds__(256) void accum_kernel(
    const float* __restrict__ rep,            // [BS, CREP, H, W]
    const int*   __restrict__ pmi,            // [BS, H, W, 4]
    const int*   __restrict__ target,         // [BS, H, W]
    const int*   __restrict__ smask,          // [H, W]
    const unsigned char* __restrict__ cond)   // [BS, H, W] bool
{
    __shared__ float s_acc[NWARP][NSEG][CPAD];   // per-warp, race-free across warps
    __shared__ float s_cnt[NWARP][NSEG];

    const int tid  = threadIdx.x;
    const int wid  = tid >> 5;
    const int lane = tid & 31;

    for (int i = tid; i < NWARP * NSEG * CPAD; i += blockDim.x)
        (&s_acc[0][0][0])[i] = 0.0f;
    for (int i = tid; i < NWARP * NSEG; i += blockDim.x)
        (&s_cnt[0][0])[i] = 0.0f;
    __syncthreads();

    const uint32_t acc_base = smem_u32(&s_acc[wid][0][0]);
    const uint32_t cnt_base = smem_u32(&s_cnt[wid][0]);

    const int stride = gridDim.x * blockDim.x;
    for (int idx = blockIdx.x * blockDim.x + tid; idx < NPIX; idx += stride) {
        const int hw  = idx % HWSZ;
        const int b   = idx / HWSZ;
        const int tgt = target[idx];
        bool valid = (tgt != 0);
        valid = valid && (cond[idx] != 0);
        valid = valid && (smask[hw] == 1);

        const unsigned vm = __ballot_sync(0xffffffffu, valid);
        if (valid) {
            // micro-proto index at the target class (tgt in {1,2,3} here)
            const int4 p4 = reinterpret_cast<const int4*>(pmi)[idx];
            const int pidx = (tgt == 1) ? p4.y : ((tgt == 2) ? p4.z : p4.w);
            const int seg = tgt * NMP + pidx;

            // load all 16 channels (coalesced across valid lanes, high MLP)
            float r[CREP];
            const float* rp = rep + (size_t)b * CREP * HWSZ + hw;
            #pragma unroll
            for (int c = 0; c < CREP; ++c) r[c] = rp[(size_t)c * HWSZ];

            // dedup within the warp: one leader per seg-group
            const unsigned peers = __match_any_sync(vm, seg);
            const uint32_t lead  = (lane == (__ffs(peers) - 1)) ? 1u : 0u;

            // leader bumps the count by the group size (atomic-free for singletons
            // would race with other groups' leaders? no — distinct seg => distinct
            // address; use predicated red for simplicity, 1 lane per group)
            {
                const uint32_t caddr = cnt_base + (uint32_t)seg * 4u;
                const float cv = (float)__popc(peers);
                asm volatile(
                    "{ .reg .pred p; setp.ne.u32 p, %0, 0;\n\t"
                    "@p red.shared.add.f32 [%1], %2; }"
                    :: "r"(lead), "r"(caddr), "f"(cv) : "memory");
            }

            // 8 paired channel updates: leaders take the fast non-atomic f32x2
            // path; rare non-leader peers use red.shared. Same warp => shared
            // ops are program-ordered, so leader RMW vs peer RED cannot race.
            const uint32_t saddr0 = acc_base + (uint32_t)seg * (CPAD * 4u);
            #pragma unroll
            for (int k = 0; k < CREP / 2; ++k) {
                const uint32_t a  = saddr0 + (uint32_t)k * 8u;
                const float vlo = r[2 * k], vhi = r[2 * k + 1];
                uint64_t vpair;
                asm("mov.b64 %0, {%1, %2};" : "=l"(vpair) : "f"(vlo), "f"(vhi));
                asm volatile(
                    "{ .reg .pred p; .reg .b64 t;\n\t"
                    "setp.ne.u32 p, %0, 0;\n\t"
                    "@p ld.shared.b64 t, [%1];\n\t"
                    "@p add.rn.f32x2 t, t, %2;\n\t"
                    "@p st.shared.b64 [%1], t;\n\t"
                    "@!p red.shared.add.f32 [%1], %3;\n\t"
                    "@!p red.shared.add.f32 [%1+4], %4;\n\t"
                    "}"
                    :: "r"(lead), "r"(a), "l"(vpair), "f"(vlo), "f"(vhi)
                    : "memory");
            }
        }
    }
    __syncthreads();

    // Block -> global reduction: 256 sum cells + 16 counts
    if (tid < NSEG * CREP) {
        const int seg = tid / CREP, c = tid % CREP;
        float v = 0.0f;
        #pragma unroll
        for (int w = 0; w < NWARP; ++w) v += s_acc[w][seg][c];
        if (v != 0.0f) atomicAdd(&g_sums[tid], v);
    }
    if (tid < NSEG) {
        float v = 0.0f;
        #pragma unroll
        for (int w = 0; w < NWARP; ++w) v += s_cnt[w][tid];
        if (v != 0.0f) atomicAdd(&g_counts[tid], v);
    }
}

__global__ void final_kernel(const float* __restrict__ protos,
                             float* __restrict__ out)
{
    const int t = threadIdx.x;                 // 256 threads, one per (seg,c)
    if (t >= NSEG * CREP) return;
    const int seg = t / CREP;
    const float p   = protos[t];
    const float cnt = g_counts[seg];
    const float mean = g_sums[t] / fmaxf(cnt, 1.0f);
    out[t] = (cnt > 0.0f) ? (0.99f * p + 0.01f * mean) : p;
}

extern "C" void kernel_launch(void* const* d_in, const int* in_sizes, int n_in,
                              void* d_out, int out_size)
{
    const float*         rep    = (const float*)d_in[0];
    const int*           pmi    = (const int*)d_in[1];
    const int*           target = (const int*)d_in[2];
    const int*           smask  = (const int*)d_in[3];
    const unsigned char* cond   = (const unsigned char*)d_in[4];
    const float*         protos = (const float*)d_in[5];
    float*               out    = (float*)d_out;

    zero_kernel<<<1, 256>>>();
    accum_kernel<<<1184, 256>>>(rep, pmi, target, smask, cond);
    final_kernel<<<1, 256>>>(protos, out);
}

// round 15
// speedup vs baseline: 1.0050x; 1.0050x over previous
#include <cuda_runtime.h>
#include <cuda_bf16.h>
#include <cstdint>

// Problem constants (fixed by reference)
#define BS   24
#define CREP 16
#define HH   320
#define WW   320
#define HWSZ (HH * WW)               // 102400
#define NPIX (BS * HWSZ)             // 2457600
#define NMP  4
#define NSEG 16                      // NUM_CLASSES * NUM_MICRO_PROTO
#define NWARP 8                      // warps per block
#define CPAD 18                      // padded channel stride (bank-conflict-free f32x2)

// Scratch (no allocations allowed): global segment sums + counts
__device__ float g_sums[NSEG * CREP];
__device__ float g_counts[NSEG];

__global__ void zero_kernel() {
    int t = threadIdx.x;
    if (t < NSEG * CREP) g_sums[t] = 0.0f;
    if (t < NSEG)        g_counts[t] = 0.0f;
}

__device__ __forceinline__ uint32_t smem_u32(const void* p) {
    uint32_t a;
    asm("{ .reg .u64 t; cvta.to.shared.u64 t, %1; cvt.u32.u64 %0, t; }"
        : "=r"(a) : "l"(p));
    return a;
}

__global__ __launch_bounds__(256) void accum_kernel(
    const float* __restrict__ rep,            // [BS, CREP, H, W]
    const int*   __restrict__ pmi,            // [BS, H, W, 4]
    const int*   __restrict__ target,         // [BS, H, W]
    const int*   __restrict__ smask,          // [H, W]
    const unsigned char* __restrict__ cond)   // [BS, H, W] bool
{
    __shared__ float s_acc[NWARP][NSEG][CPAD];   // per-warp, race-free across warps
    __shared__ float s_cnt[NWARP][NSEG];

    const int tid  = threadIdx.x;
    const int wid  = tid >> 5;
    const int lane = tid & 31;

    for (int i = tid; i < NWARP * NSEG * CPAD; i += blockDim.x)
        (&s_acc[0][0][0])[i] = 0.0f;
    for (int i = tid; i < NWARP * NSEG; i += blockDim.x)
        (&s_cnt[0][0])[i] = 0.0f;
    __syncthreads();

    const uint32_t acc_base = smem_u32(&s_acc[wid][0][0]);
    const uint32_t cnt_base = smem_u32(&s_cnt[wid][0]);

    const int stride = gridDim.x * blockDim.x;
    for (int idx = blockIdx.x * blockDim.x + tid; idx < NPIX; idx += stride) {
        const int hw  = idx % HWSZ;
        const int b   = idx / HWSZ;
        const int tgt = target[idx];
        bool valid = (tgt != 0);
        valid = valid && (cond[idx] != 0);
        valid = valid && (smask[hw] == 1);

        const unsigned vm = __ballot_sync(0xffffffffu, valid);
        if (valid) {
            // micro-proto index at the target class (tgt in {1,2,3} here)
            const int4 p4 = reinterpret_cast<const int4*>(pmi)[idx];
            const int pidx = (tgt == 1) ? p4.y : ((tgt == 2) ? p4.z : p4.w);
            const int seg = tgt * NMP + pidx;

            // load all 16 channels (coalesced across valid lanes, high MLP)
            float r[CREP];
            const float* rp = rep + (size_t)b * CREP * HWSZ + hw;
            #pragma unroll
            for (int c = 0; c < CREP; ++c) r[c] = rp[(size_t)c * HWSZ];

            // dedup within the warp: one leader per seg-group
            const unsigned peers = __match_any_sync(vm, seg);
            const uint32_t lead  = (lane == (__ffs(peers) - 1)) ? 1u : 0u;

            // leader bumps the count by the group size (atomic-free for singletons
            // would race with other groups' leaders? no — distinct seg => distinct
            // address; use predicated red for simplicity, 1 lane per group)
            {
                const uint32_t caddr = cnt_base + (uint32_t)seg * 4u;
                const float cv = (float)__popc(peers);
                asm volatile(
                    "{ .reg .pred p; setp.ne.u32 p, %0, 0;\n\t"
                    "@p red.shared.add.f32 [%1], %2; }"
                    :: "r"(lead), "r"(caddr), "f"(cv) : "memory");
            }

            // 8 paired channel updates: leaders take the fast non-atomic f32x2
            // path; rare non-leader peers use red.shared. Same warp => shared
            // ops are program-ordered, so leader RMW vs peer RED cannot race.
            const uint32_t saddr0 = acc_base + (uint32_t)seg * (CPAD * 4u);
            #pragma unroll
            for (int k = 0; k < CREP / 2; ++k) {
                const uint32_t a  = saddr0 + (uint32_t)k * 8u;
                const float vlo = r[2 * k], vhi = r[2 * k + 1];
                uint64_t vpair;
                asm("mov.b64 %0, {%1, %2};" : "=l"(vpair) : "f"(vlo), "f"(vhi));
                asm volatile(
                    "{ .reg .pred p; .reg .b64 t;\n\t"
                    "setp.ne.u32 p, %0, 0;\n\t"
                    "@p ld.shared.b64 t, [%1];\n\t"
                    "@p add.rn.f32x2 t, t, %2;\n\t"
                    "@p st.shared.b64 [%1], t;\n\t"
                    "@!p red.shared.add.f32 [%1], %3;\n\t"
                    "@!p red.shared.add.f32 [%1+4], %4;\n\t"
                    "}"
                    :: "r"(lead), "r"(a), "l"(vpair), "f"(vlo), "f"(vhi)
                    : "memory");
            }
        }
    }
    __syncthreads();

    // Block -> global reduction: 256 sum cells + 16 counts
    if (tid < NSEG * CREP) {
        const int seg = tid / CREP, c = tid % CREP;
        float v = 0.0f;
        #pragma unroll
        for (int w = 0; w < NWARP; ++w) v += s_acc[w][seg][c];
        if (v != 0.0f) atomicAdd(&g_sums[tid], v);
    }
    if (tid < NSEG) {
        float v = 0.0f;
        #pragma unroll
        for (int w = 0; w < NWARP; ++w) v += s_cnt[w][tid];
        if (v != 0.0f) atomicAdd(&g_counts[tid], v);
    }
}

__global__ void final_kernel(const float* __restrict__ protos,
                             float* __restrict__ out)
{
    const int t = threadIdx.x;                 // 256 threads, one per (seg,c)
    if (t >= NSEG * CREP) return;
    const int seg = t / CREP;
    const float p   = protos[t];
    const float cnt = g_counts[seg];
    const float mean = g_sums[t] / fmaxf(cnt, 1.0f);
    out[t] = (cnt > 0.0f) ? (0.99f * p + 0.01f * mean) : p;
}

extern "C" void kernel_launch(void* const* d_in, const int* in_sizes, int n_in,
                              void* d_out, int out_size)
{
    const float*         rep    = (const float*)d_in[0];
    const int*           pmi    = (const int*)d_in[1];
    const int*           target = (const int*)d_in[2];
    const int*           smask  = (const int*)d_in[3];
    const unsigned char* cond   = (const unsigned char*)d_in[4];
    const float*         protos = (const float*)d_in[5];
    float*               out    = (float*)d_out;

    zero_kernel<<<1, 256>>>();
    accum_kernel<<<1184, 256>>>(rep, pmi, target, smask, cond);
    final_kernel<<<1, 256>>>(protos, out);
}